// round 1
// baseline (speedup 1.0000x reference)
#include <cuda_runtime.h>
#include <math.h>

#define NB 2
#define NP 8192
#define DD 64
#define KK 20
#define NS 8
#define CH (NP/NS)
#define TS 64
#define EPSB 1e-5f

// ---------------- scratch (device globals: allocation-free) ----------------
__device__ float d_hfT[(size_t)NB*NP*DD];     // fused features, point-major (B,N,64)
__device__ float d_sqn[(size_t)NB*NP];        // squared norms
__device__ float d_G  [(size_t)NB*NP*DD];     // W1 * h  (point-major)
__device__ float d_A  [(size_t)NB*NP*DD];     // (W2-W1) * h (point-major)
__device__ float d_xT [(size_t)NB*NP*4];      // x transposed+padded (B,N,4)
__device__ int   d_nidx[(size_t)NB*NP*KK];    // final knn indices
__device__ float d_scV[(size_t)NB*NP*NS*KK];  // per-chunk top-k values
__device__ int   d_scI[(size_t)NB*NP*NS*KK];  // per-chunk top-k indices

// ---------------- helpers ----------------
union U64F2 { unsigned long long u; float2 f; };

__device__ __forceinline__ unsigned long long ffma2(unsigned long long a,
                                                    unsigned long long b,
                                                    unsigned long long c) {
    unsigned long long d;
    asm("fma.rn.f32x2 %0, %1, %2, %3;" : "=l"(d) : "l"(a), "l"(b), "l"(c));
    return d;
}
__device__ __forceinline__ unsigned long long fadd2(unsigned long long a,
                                                    unsigned long long b) {
    unsigned long long d;
    asm("add.rn.f32x2 %0, %1, %2;" : "=l"(d) : "l"(a), "l"(b));
    return d;
}

// top-k insertion with jax.lax.top_k tie-break (value desc, index asc)
__device__ __forceinline__ void topk_insert(float* tv, int* ti, float v, int m,
                                            float& thr, int& thrI) {
    if (v > thr || (v == thr && m < thrI)) {
        int p = KK - 1;
        while (p > 0) {
            float pv = tv[p-1]; int pi = ti[p-1];
            if (v > pv || (v == pv && m < pi)) { tv[p] = pv; ti[p] = pi; --p; }
            else break;
        }
        tv[p] = v; ti[p] = m;
        thr = tv[KK-1]; thrI = ti[KK-1];
    }
}

// ---------------- x -> xT (B,N,4) + squared norms ----------------
__global__ void prep_x_kernel(const float* __restrict__ x) {
    int i = blockIdx.x * blockDim.x + threadIdx.x;   // b*NP+n
    if (i >= NB*NP) return;
    int b = i >> 13, n = i & (NP - 1);
    const float* xb = x + (size_t)b * 3 * NP;
    float a0 = xb[0*NP + n], a1 = xb[1*NP + n], a2 = xb[2*NP + n];
    float4 v = make_float4(a0, a1, a2, 0.f);
    *reinterpret_cast<float4*>(d_xT + (size_t)i * 4) = v;
    d_sqn[i] = a0*a0 + a1*a1 + a2*a2;
}

// ---------------- layer0 G/A from x (W0 is 64x6) ----------------
__global__ void ga0_kernel(const float* __restrict__ W0) {
    int b = blockIdx.y;
    int n0 = blockIdx.x * 16;
    int o = threadIdx.x;         // 0..127
    float w0, w1, w2;
    if (o < 64) { w0 = W0[o*6+0]; w1 = W0[o*6+1]; w2 = W0[o*6+2]; }
    else { int u = o - 64;
           w0 = W0[u*6+3] - W0[u*6+0];
           w1 = W0[u*6+4] - W0[u*6+1];
           w2 = W0[u*6+5] - W0[u*6+2]; }
    float* dst = (o < 64) ? d_G : d_A;
    int oo = o & 63;
    #pragma unroll
    for (int p = 0; p < 16; p++) {
        float4 xv = *reinterpret_cast<const float4*>(d_xT + ((size_t)b*NP + n0 + p) * 4);
        float v = w0*xv.x + w1*xv.y + w2*xv.z;
        dst[((size_t)b*NP + n0 + p)*DD + oo] = v;
    }
}

// ---------------- kNN: per-chunk top-20 ----------------
template<int C>
__global__ void knn_kernel() {
    const int b = blockIdx.z, s = blockIdx.y;
    const int q = blockIdx.x * blockDim.x + threadIdx.x;
    const float* pts = (C == 4) ? d_xT : d_hfT;
    const float* P = pts + (size_t)b * NP * C;

    unsigned long long qp[C/2];
    #pragma unroll
    for (int j = 0; j < C/4; j++) {
        float4 v = *reinterpret_cast<const float4*>(P + (size_t)q * C + 4*j);
        U64F2 lo, hi;
        lo.f = make_float2(v.x, v.y);
        hi.f = make_float2(v.z, v.w);
        qp[2*j]   = lo.u;
        qp[2*j+1] = hi.u;
    }
    const float sqq = d_sqn[b*NP + q];

    float tv[KK]; int ti[KK];
    #pragma unroll
    for (int i = 0; i < KK; i++) { tv[i] = -INFINITY; ti[i] = 0x7FFFFFFF; }
    float thr = -INFINITY; int thrI = 0x7FFFFFFF;

    __shared__ __align__(16) float smC[TS * C];
    __shared__ float smS[TS];

    for (int tile = 0; tile < CH / TS; tile++) {
        const int m0 = s * CH + tile * TS;
        __syncthreads();
        const float4* src = reinterpret_cast<const float4*>(P + (size_t)m0 * C);
        for (int t = threadIdx.x; t < TS * C / 4; t += blockDim.x)
            reinterpret_cast<float4*>(smC)[t] = src[t];
        for (int t = threadIdx.x; t < TS; t += blockDim.x)
            smS[t] = d_sqn[b*NP + m0 + t];
        __syncthreads();

        for (int t = 0; t < TS; t++) {
            const unsigned long long* cp =
                reinterpret_cast<const unsigned long long*>(smC + t * C);
            unsigned long long accu;
            if constexpr (C >= 8) {
                unsigned long long a0 = 0ull, a1 = 0ull, a2 = 0ull, a3 = 0ull;
                #pragma unroll
                for (int j = 0; j < C/2; j += 4) {
                    a0 = ffma2(qp[j],   cp[j],   a0);
                    a1 = ffma2(qp[j+1], cp[j+1], a1);
                    a2 = ffma2(qp[j+2], cp[j+2], a2);
                    a3 = ffma2(qp[j+3], cp[j+3], a3);
                }
                accu = fadd2(fadd2(a0, a1), fadd2(a2, a3));
            } else {
                accu = ffma2(qp[1], cp[1], ffma2(qp[0], cp[0], 0ull));
            }
            U64F2 r; r.u = accu;
            float dot  = r.f.x + r.f.y;
            float negd = 2.0f * dot - sqq - smS[t];
            topk_insert(tv, ti, negd, m0 + t, thr, thrI);
        }
    }

    size_t off = ((size_t)(b*NP + q) * NS + s) * KK;
    #pragma unroll
    for (int i = 0; i < KK; i++) { d_scV[off+i] = tv[i]; d_scI[off+i] = ti[i]; }
}

// ---------------- merge per-chunk lists -> final top-20 ----------------
__global__ void merge_kernel() {
    int i = blockIdx.x * blockDim.x + threadIdx.x;   // b*NP+n
    if (i >= NB*NP) return;
    float tv[KK]; int ti[KK];
    #pragma unroll
    for (int k = 0; k < KK; k++) { tv[k] = -INFINITY; ti[k] = 0x7FFFFFFF; }
    float thr = -INFINITY; int thrI = 0x7FFFFFFF;
    size_t base = (size_t)i * NS * KK;
    for (int e = 0; e < NS*KK; e++) {
        float v = d_scV[base + e];
        int   m = d_scI[base + e];
        topk_insert(tv, ti, v, m, thr, thrI);
    }
    #pragma unroll
    for (int k = 0; k < KK; k++) d_nidx[(size_t)i*KK + k] = ti[k];
}

// ---------------- gather-max + BN + lrelu -> h (channel-major output) ------
__global__ void gather_kernel(const float* __restrict__ gamma,
                              const float* __restrict__ beta,
                              const float* __restrict__ mean,
                              const float* __restrict__ var,
                              float* __restrict__ out) {
    int b = blockIdx.y;
    int j = threadIdx.x >> 6;     // point within block (0..3)
    int o = threadIdx.x & 63;
    int n = blockIdx.x * 4 + j;

    __shared__ int sIdx[4 * KK];
    if (threadIdx.x < 4 * KK) {
        int jj = threadIdx.x / KK, kk = threadIdx.x % KK;
        sIdx[threadIdx.x] = d_nidx[((size_t)b*NP + blockIdx.x*4 + jj)*KK + kk];
    }
    __syncthreads();

    const float* Gb = d_G + (size_t)b * NP * DD;
    float mx = -INFINITY;
    #pragma unroll
    for (int k = 0; k < KK; k++)
        mx = fmaxf(mx, Gb[(size_t)sIdx[j*KK + k] * DD + o]);

    float z = d_A[((size_t)b*NP + n)*DD + o] + mx;
    float sc = gamma[o] * rsqrtf(var[o] + EPSB);
    z = (z - mean[o]) * sc + beta[o];
    z = (z >= 0.f) ? z : 0.2f * z;
    out[((size_t)b*DD + o)*NP + n] = z;
}

// ---------------- fuse: hf = elu(Wf * [h; rep]) -> point-major ----------------
__global__ void fuse_kernel(const float* __restrict__ h,
                            const float* __restrict__ rep,
                            const float* __restrict__ W) {
    int b = blockIdx.y;
    int n0 = blockIdx.x * 16;
    int o = threadIdx.x;          // 0..63

    __shared__ float sWT[128][64];
    __shared__ float sIn[128][16];
    for (int t = threadIdx.x; t < 128*64; t += 64) {
        int c = t >> 6, oo = t & 63;
        sWT[c][oo] = W[oo*128 + c];
    }
    for (int t = threadIdx.x; t < 128*16; t += 64) {
        int c = t >> 4, p = t & 15;
        sIn[c][p] = (c < 64) ? h  [((size_t)b*DD + c)*NP + n0 + p]
                             : rep[((size_t)b*DD + (c-64))*NP + n0 + p];
    }
    __syncthreads();

    float acc[16];
    #pragma unroll
    for (int p = 0; p < 16; p++) acc[p] = 0.f;
    for (int c = 0; c < 128; c++) {
        float w = sWT[c][o];
        #pragma unroll
        for (int p = 0; p < 16; p++) acc[p] = fmaf(w, sIn[c][p], acc[p]);
    }
    #pragma unroll
    for (int p = 0; p < 16; p++) {
        float z = acc[p];
        z = (z > 0.f) ? z : expm1f(z);
        d_hfT[((size_t)b*NP + n0 + p)*DD + o] = z;
    }
}

// ---------------- squared norms of hfT ----------------
__global__ void sqnorm_kernel() {
    int i = blockIdx.x * blockDim.x + threadIdx.x;   // point index
    if (i >= NB*NP) return;
    const float4* r = reinterpret_cast<const float4*>(d_hfT + (size_t)i * DD);
    float s = 0.f;
    #pragma unroll
    for (int j = 0; j < 16; j++) {
        float4 v = r[j];
        s += v.x*v.x + v.y*v.y + v.z*v.z + v.w*v.w;
    }
    d_sqn[i] = s;
}

// ---------------- G/A from hfT (W is 64x128) ----------------
__global__ void ga_kernel(const float* __restrict__ W) {
    int b = blockIdx.y;
    int n0 = blockIdx.x * 16;
    int o = threadIdx.x;          // 0..127

    __shared__ float sWT[64][128];   // [c][o128]
    __shared__ float sIn[16][64];
    for (int c = 0; c < 64; c++) {
        float w = (o < 64) ? W[o*128 + c]
                           : (W[(o-64)*128 + 64 + c] - W[(o-64)*128 + c]);
        sWT[c][o] = w;
    }
    for (int t = threadIdx.x; t < 16*64; t += 128) {
        int p = t >> 6, c = t & 63;
        sIn[p][c] = d_hfT[((size_t)b*NP + n0 + p)*DD + c];
    }
    __syncthreads();

    float acc[16];
    #pragma unroll
    for (int p = 0; p < 16; p++) acc[p] = 0.f;
    for (int c = 0; c < 64; c++) {
        float w = sWT[c][o];
        #pragma unroll
        for (int p = 0; p < 16; p++) acc[p] = fmaf(w, sIn[p][c], acc[p]);
    }
    float* dst = (o < 64) ? d_G : d_A;
    int oo = o & 63;
    #pragma unroll
    for (int p = 0; p < 16; p++)
        dst[((size_t)b*NP + n0 + p)*DD + oo] = acc[p];
}

// ---------------- launch ----------------
extern "C" void kernel_launch(void* const* d_in, const int* in_sizes, int n_in,
                              void* d_out, int out_size) {
    (void)in_sizes; (void)n_in; (void)out_size;
    const float* x     = (const float*)d_in[0];
    const float* reps  = (const float*)d_in[1];
    const float* w0    = (const float*)d_in[2];
    const float* convw = (const float*)d_in[3];
    const float* gam   = (const float*)d_in[4];
    const float* bet   = (const float*)d_in[5];
    const float* rm    = (const float*)d_in[6];
    const float* rv    = (const float*)d_in[7];
    const float* fw    = (const float*)d_in[8];
    float* out = (float*)d_out;
    const size_t LSZ = (size_t)NB * DD * NP;

    // layer 0
    prep_x_kernel<<<NB*NP/256, 256>>>(x);
    ga0_kernel<<<dim3(NP/16, NB), 128>>>(w0);
    knn_kernel<4><<<dim3(NP/256, NS, NB), 256>>>();
    merge_kernel<<<NB*NP/256, 256>>>();
    gather_kernel<<<dim3(NP/4, NB), 256>>>(gam, bet, rm, rv, out);

    // layers 1..3
    for (int i = 0; i < 3; i++) {
        fuse_kernel<<<dim3(NP/16, NB), 64>>>(out + (size_t)i * LSZ,
                                             reps + (size_t)i * LSZ,
                                             fw + (size_t)i * 64 * 128);
        sqnorm_kernel<<<NB*NP/256, 256>>>();
        ga_kernel<<<dim3(NP/16, NB), 128>>>(convw + (size_t)i * 64 * 128);
        knn_kernel<64><<<dim3(NP/256, NS, NB), 256>>>();
        merge_kernel<<<NB*NP/256, 256>>>();
        gather_kernel<<<dim3(NP/4, NB), 256>>>(gam + (i+1)*64, bet + (i+1)*64,
                                               rm + (i+1)*64, rv + (i+1)*64,
                                               out + (size_t)(i+1) * LSZ);
    }
}

// round 2
// speedup vs baseline: 4.7361x; 4.7361x over previous
#include <cuda_runtime.h>
#include <math.h>

#define NB 2
#define NP 8192
#define DD 64
#define KK 20
#define NS 4
#define CH (NP/NS)
#define TS 64
#define BUF 4
#define EPSB 1e-5f

// ---------------- scratch (device globals: allocation-free) ----------------
__device__ float d_hfT[(size_t)NB*NP*DD];     // fused features, point-major (B,N,64)
__device__ float d_sqn[(size_t)NB*NP];        // squared norms
__device__ float d_G  [(size_t)NB*NP*DD];     // W1 * h  (point-major)
__device__ float d_A  [(size_t)NB*NP*DD];     // (W2-W1) * h (point-major)
__device__ float d_xT [(size_t)NB*NP*4];      // x transposed+padded (B,N,4)
__device__ int   d_nidx[(size_t)NB*NP*KK];    // final knn indices
__device__ float d_scV[(size_t)NB*NP*NS*KK];  // per-chunk top-k values
__device__ int   d_scI[(size_t)NB*NP*NS*KK];  // per-chunk top-k indices

// ---------------- helpers ----------------
union U64F2 { unsigned long long u; float2 f; };

__device__ __forceinline__ unsigned long long ffma2(unsigned long long a,
                                                    unsigned long long b,
                                                    unsigned long long c) {
    unsigned long long d;
    asm("fma.rn.f32x2 %0, %1, %2, %3;" : "=l"(d) : "l"(a), "l"(b), "l"(c));
    return d;
}
__device__ __forceinline__ unsigned long long fadd2(unsigned long long a,
                                                    unsigned long long b) {
    unsigned long long d;
    asm("add.rn.f32x2 %0, %1, %2;" : "=l"(d) : "l"(a), "l"(b));
    return d;
}
__device__ __forceinline__ unsigned long long packf2(float x, float y) {
    return (unsigned long long)__float_as_uint(x) |
           ((unsigned long long)__float_as_uint(y) << 32);
}

// Branch-free sorted insert, values in regs, indices in column-major smem.
// Strict '>' preserves (value desc, index asc) tie-break for index-ordered inserts.
__device__ __forceinline__ void insert_smemI(float (&tv)[KK], int (*ti)[256],
                                             int tid, float v, int idx) {
    #pragma unroll
    for (int p = 0; p < KK; p++) {
        bool sw = v > tv[p];
        if (sw) {
            float ov = tv[p]; tv[p] = v; v = ov;
            int oi = ti[p][tid]; ti[p][tid] = idx; idx = oi;
        }
    }
}

// All-register variant (for merge kernel; fully static indexing, no spills).
__device__ __forceinline__ void insert_regs(float (&tv)[KK], int (&ti)[KK],
                                            float v, int idx) {
    #pragma unroll
    for (int p = 0; p < KK; p++) {
        bool sw = v > tv[p];
        float ov = tv[p]; int oi = ti[p];
        tv[p] = sw ? v : ov;  ti[p] = sw ? idx : oi;
        v = sw ? ov : v;      idx = sw ? oi : idx;
    }
}

// ---------------- x -> xT (B,N,4) + squared norms ----------------
__global__ void prep_x_kernel(const float* __restrict__ x) {
    int i = blockIdx.x * blockDim.x + threadIdx.x;   // b*NP+n
    if (i >= NB*NP) return;
    int b = i >> 13, n = i & (NP - 1);
    const float* xb = x + (size_t)b * 3 * NP;
    float a0 = xb[0*NP + n], a1 = xb[1*NP + n], a2 = xb[2*NP + n];
    float4 v = make_float4(a0, a1, a2, 0.f);
    *reinterpret_cast<float4*>(d_xT + (size_t)i * 4) = v;
    d_sqn[i] = a0*a0 + a1*a1 + a2*a2;
}

// ---------------- layer0 G/A from x (W0 is 64x6) ----------------
__global__ void ga0_kernel(const float* __restrict__ W0) {
    int b = blockIdx.y;
    int n0 = blockIdx.x * 16;
    int o = threadIdx.x;         // 0..127
    float w0, w1, w2;
    if (o < 64) { w0 = W0[o*6+0]; w1 = W0[o*6+1]; w2 = W0[o*6+2]; }
    else { int u = o - 64;
           w0 = W0[u*6+3] - W0[u*6+0];
           w1 = W0[u*6+4] - W0[u*6+1];
           w2 = W0[u*6+5] - W0[u*6+2]; }
    float* dst = (o < 64) ? d_G : d_A;
    int oo = o & 63;
    #pragma unroll
    for (int p = 0; p < 16; p++) {
        float4 xv = *reinterpret_cast<const float4*>(d_xT + ((size_t)b*NP + n0 + p) * 4);
        float v = w0*xv.x + w1*xv.y + w2*xv.z;
        dst[((size_t)b*NP + n0 + p)*DD + oo] = v;
    }
}

// ---------------- kNN v2: per-chunk top-20, buffered filtering ----------------
template<int C>
__global__ void __launch_bounds__(256, 2) knn2_kernel() {
    const int b = blockIdx.z, s = blockIdx.y;
    const int tid = threadIdx.x;
    const int q = blockIdx.x * 256 + tid;
    const float* pts = (C == 4) ? d_xT : d_hfT;
    const float* P = pts + (size_t)b * NP * C;

    __shared__ __align__(16) float smC[TS * C];
    __shared__ float smS[TS];
    __shared__ float sBufV[BUF][256];
    __shared__ int   sBufI[BUF][256];
    __shared__ int   sTi[KK][256];

    // query vector in packed f32x2 registers
    unsigned long long qp[C/2];
    #pragma unroll
    for (int j = 0; j < C/4; j++) {
        float4 v = *reinterpret_cast<const float4*>(P + (size_t)q * C + 4*j);
        qp[2*j]   = packf2(v.x, v.y);
        qp[2*j+1] = packf2(v.z, v.w);
    }
    const float sqq = d_sqn[b*NP + q];

    float tv[KK];
    #pragma unroll
    for (int i = 0; i < KK; i++) { tv[i] = -INFINITY; sTi[i][tid] = 0x7FFFFFFF; }
    float thrK = -INFINITY;
    int cnt = 0;

    const unsigned int saTile =
        (unsigned int)__cvta_generic_to_shared(smC);

    for (int tile = 0; tile < CH / TS; tile++) {
        const int m0 = s * CH + tile * TS;
        __syncthreads();
        const float4* src = reinterpret_cast<const float4*>(P + (size_t)m0 * C);
        for (int t = tid; t < TS * C / 4; t += 256)
            reinterpret_cast<float4*>(smC)[t] = src[t];
        if (tid < TS) smS[tid] = d_sqn[b*NP + m0 + tid];
        __syncthreads();

        #pragma unroll 1
        for (int t = 0; t < TS; t++) {
            unsigned int ca = saTile + (unsigned int)(t * C * 4);
            float key;
            if constexpr (C >= 8) {
                unsigned long long a0 = 0ull, a1 = 0ull, a2 = 0ull, a3 = 0ull;
                #pragma unroll
                for (int j = 0; j < C/4; j++) {
                    unsigned long long x0, x1;
                    asm("ld.shared.v2.b64 {%0,%1},[%2];"
                        : "=l"(x0), "=l"(x1) : "r"(ca + j*16));
                    if ((j & 1) == 0) { a0 = ffma2(qp[2*j], x0, a0); a1 = ffma2(qp[2*j+1], x1, a1); }
                    else              { a2 = ffma2(qp[2*j], x0, a2); a3 = ffma2(qp[2*j+1], x1, a3); }
                }
                U64F2 r; r.u = fadd2(fadd2(a0, a1), fadd2(a2, a3));
                float dot = r.f.x + r.f.y;
                key = fmaf(2.0f, dot, -smS[t]);
            } else {
                unsigned long long x0, x1;
                asm("ld.shared.v2.b64 {%0,%1},[%2];"
                    : "=l"(x0), "=l"(x1) : "r"(ca));
                U64F2 r; r.u = fadd2(ffma2(qp[0], x0, 0ull), ffma2(qp[1], x1, 0ull));
                float dot = r.f.x + r.f.y;
                key = fmaf(2.0f, dot, -smS[t]);
            }
            if (key > thrK) {
                sBufV[cnt][tid] = key; sBufI[cnt][tid] = m0 + t; cnt++;
            }
            if (__any_sync(0xffffffffu, cnt == BUF)) {
                #pragma unroll 1
                for (int e = 0; e < cnt; e++)
                    insert_smemI(tv, sTi, tid, sBufV[e][tid], sBufI[e][tid]);
                cnt = 0; thrK = tv[KK-1];
            }
        }
    }
    #pragma unroll 1
    for (int e = 0; e < cnt; e++)
        insert_smemI(tv, sTi, tid, sBufV[e][tid], sBufI[e][tid]);

    size_t off = ((size_t)(b*NP + q) * NS + s) * KK;
    #pragma unroll
    for (int i = 0; i < KK; i++) {
        d_scV[off+i] = tv[i] - sqq;         // restore true neg-distance
        d_scI[off+i] = sTi[i][tid];
    }
}

// ---------------- merge per-chunk lists -> final top-20 ----------------
__global__ void merge_kernel() {
    int i = blockIdx.x * blockDim.x + threadIdx.x;   // b*NP+n
    if (i >= NB*NP) return;
    float tv[KK]; int ti[KK];
    #pragma unroll
    for (int k = 0; k < KK; k++) { tv[k] = -INFINITY; ti[k] = 0x7FFFFFFF; }
    float thr = -INFINITY;
    size_t base = (size_t)i * NS * KK;
    #pragma unroll 1
    for (int e = 0; e < NS*KK; e++) {
        float v = d_scV[base + e];
        int   m = d_scI[base + e];
        if (v > thr) { insert_regs(tv, ti, v, m); thr = tv[KK-1]; }
    }
    #pragma unroll
    for (int k = 0; k < KK; k++) d_nidx[(size_t)i*KK + k] = ti[k];
}

// ---------------- gather-max + BN + lrelu -> h (channel-major output) ------
__global__ void gather_kernel(const float* __restrict__ gamma,
                              const float* __restrict__ beta,
                              const float* __restrict__ mean,
                              const float* __restrict__ var,
                              float* __restrict__ out) {
    int b = blockIdx.y;
    int j = threadIdx.x >> 6;     // point within block (0..3)
    int o = threadIdx.x & 63;
    int n = blockIdx.x * 4 + j;

    __shared__ int sIdx[4 * KK];
    if (threadIdx.x < 4 * KK) {
        int jj = threadIdx.x / KK, kk = threadIdx.x % KK;
        sIdx[threadIdx.x] = d_nidx[((size_t)b*NP + blockIdx.x*4 + jj)*KK + kk];
    }
    __syncthreads();

    const float* Gb = d_G + (size_t)b * NP * DD;
    float mx = -INFINITY;
    #pragma unroll
    for (int k = 0; k < KK; k++)
        mx = fmaxf(mx, Gb[(size_t)sIdx[j*KK + k] * DD + o]);

    float z = d_A[((size_t)b*NP + n)*DD + o] + mx;
    float sc = gamma[o] * rsqrtf(var[o] + EPSB);
    z = (z - mean[o]) * sc + beta[o];
    z = (z >= 0.f) ? z : 0.2f * z;
    out[((size_t)b*DD + o)*NP + n] = z;
}

// ---------------- fuse: hf = elu(Wf * [h; rep]) -> point-major ----------------
__global__ void fuse_kernel(const float* __restrict__ h,
                            const float* __restrict__ rep,
                            const float* __restrict__ W) {
    int b = blockIdx.y;
    int n0 = blockIdx.x * 16;
    int o = threadIdx.x;          // 0..63

    __shared__ float sWT[128][64];
    __shared__ float sIn[128][16];
    for (int t = threadIdx.x; t < 128*64; t += 64) {
        int c = t >> 6, oo = t & 63;
        sWT[c][oo] = W[oo*128 + c];
    }
    for (int t = threadIdx.x; t < 128*16; t += 64) {
        int c = t >> 4, p = t & 15;
        sIn[c][p] = (c < 64) ? h  [((size_t)b*DD + c)*NP + n0 + p]
                             : rep[((size_t)b*DD + (c-64))*NP + n0 + p];
    }
    __syncthreads();

    float acc[16];
    #pragma unroll
    for (int p = 0; p < 16; p++) acc[p] = 0.f;
    for (int c = 0; c < 128; c++) {
        float w = sWT[c][o];
        #pragma unroll
        for (int p = 0; p < 16; p++) acc[p] = fmaf(w, sIn[c][p], acc[p]);
    }
    #pragma unroll
    for (int p = 0; p < 16; p++) {
        float z = acc[p];
        z = (z > 0.f) ? z : expm1f(z);
        d_hfT[((size_t)b*NP + n0 + p)*DD + o] = z;
    }
}

// ---------------- squared norms of hfT ----------------
__global__ void sqnorm_kernel() {
    int i = blockIdx.x * blockDim.x + threadIdx.x;   // point index
    if (i >= NB*NP) return;
    const float4* r = reinterpret_cast<const float4*>(d_hfT + (size_t)i * DD);
    float s = 0.f;
    #pragma unroll
    for (int j = 0; j < 16; j++) {
        float4 v = r[j];
        s += v.x*v.x + v.y*v.y + v.z*v.z + v.w*v.w;
    }
    d_sqn[i] = s;
}

// ---------------- G/A from hfT (W is 64x128) ----------------
__global__ void ga_kernel(const float* __restrict__ W) {
    int b = blockIdx.y;
    int n0 = blockIdx.x * 16;
    int o = threadIdx.x;          // 0..127

    __shared__ float sWT[64][128];   // [c][o128]
    __shared__ float sIn[16][64];
    for (int c = 0; c < 64; c++) {
        float w = (o < 64) ? W[o*128 + c]
                           : (W[(o-64)*128 + 64 + c] - W[(o-64)*128 + c]);
        sWT[c][o] = w;
    }
    for (int t = threadIdx.x; t < 16*64; t += 128) {
        int p = t >> 6, c = t & 63;
        sIn[p][c] = d_hfT[((size_t)b*NP + n0 + p)*DD + c];
    }
    __syncthreads();

    float acc[16];
    #pragma unroll
    for (int p = 0; p < 16; p++) acc[p] = 0.f;
    for (int c = 0; c < 64; c++) {
        float w = sWT[c][o];
        #pragma unroll
        for (int p = 0; p < 16; p++) acc[p] = fmaf(w, sIn[p][c], acc[p]);
    }
    float* dst = (o < 64) ? d_G : d_A;
    int oo = o & 63;
    #pragma unroll
    for (int p = 0; p < 16; p++)
        dst[((size_t)b*NP + n0 + p)*DD + oo] = acc[p];
}

// ---------------- launch ----------------
extern "C" void kernel_launch(void* const* d_in, const int* in_sizes, int n_in,
                              void* d_out, int out_size) {
    (void)in_sizes; (void)n_in; (void)out_size;
    const float* x     = (const float*)d_in[0];
    const float* reps  = (const float*)d_in[1];
    const float* w0    = (const float*)d_in[2];
    const float* convw = (const float*)d_in[3];
    const float* gam   = (const float*)d_in[4];
    const float* bet   = (const float*)d_in[5];
    const float* rm    = (const float*)d_in[6];
    const float* rv    = (const float*)d_in[7];
    const float* fw    = (const float*)d_in[8];
    float* out = (float*)d_out;
    const size_t LSZ = (size_t)NB * DD * NP;

    // layer 0
    prep_x_kernel<<<NB*NP/256, 256>>>(x);
    ga0_kernel<<<dim3(NP/16, NB), 128>>>(w0);
    knn2_kernel<4><<<dim3(NP/256, NS, NB), 256>>>();
    merge_kernel<<<NB*NP/256, 256>>>();
    gather_kernel<<<dim3(NP/4, NB), 256>>>(gam, bet, rm, rv, out);

    // layers 1..3
    for (int i = 0; i < 3; i++) {
        fuse_kernel<<<dim3(NP/16, NB), 64>>>(out + (size_t)i * LSZ,
                                             reps + (size_t)i * LSZ,
                                             fw + (size_t)i * 64 * 128);
        sqnorm_kernel<<<NB*NP/256, 256>>>();
        ga_kernel<<<dim3(NP/16, NB), 128>>>(convw + (size_t)i * 64 * 128);
        knn2_kernel<64><<<dim3(NP/256, NS, NB), 256>>>();
        merge_kernel<<<NB*NP/256, 256>>>();
        gather_kernel<<<dim3(NP/4, NB), 256>>>(gam + (i+1)*64, bet + (i+1)*64,
                                               rm + (i+1)*64, rv + (i+1)*64,
                                               out + (size_t)(i+1) * LSZ);
    }
}

// round 3
// speedup vs baseline: 4.9965x; 1.0550x over previous
#include <cuda_runtime.h>
#include <math.h>

#define NB 2
#define NP 8192
#define DD 64
#define KK 20
#define NS 4
#define CH (NP/NS)
#define TS 64
#define BUF 8
#define EPSB 1e-5f

typedef unsigned long long u64;
typedef unsigned int u32;

// ---------------- scratch (device globals: allocation-free) ----------------
__device__ float d_hfT[(size_t)NB*NP*DD];     // fused features, point-major (B,N,64)
__device__ float d_sqn[(size_t)NB*NP];        // squared norms
__device__ float d_G  [(size_t)NB*NP*DD];     // W1 * h  (point-major)
__device__ float d_A  [(size_t)NB*NP*DD];     // (W2-W1) * h (point-major)
__device__ float d_xT [(size_t)NB*NP*4];      // x transposed+padded (B,N,4)
__device__ int   d_nidx[(size_t)NB*NP*KK];    // final knn indices
__device__ u64   d_scP[(size_t)NB*NP*NS*KK];  // per-chunk packed (ord(val)<<32 | ~idx)

// ---------------- helpers ----------------
union U64F2 { u64 u; float2 f; };

__device__ __forceinline__ u64 ffma2(u64 a, u64 b, u64 c) {
    u64 d;
    asm("fma.rn.f32x2 %0, %1, %2, %3;" : "=l"(d) : "l"(a), "l"(b), "l"(c));
    return d;
}
__device__ __forceinline__ u64 fadd2(u64 a, u64 b) {
    u64 d;
    asm("add.rn.f32x2 %0, %1, %2;" : "=l"(d) : "l"(a), "l"(b));
    return d;
}
__device__ __forceinline__ u64 packf2(float x, float y) {
    return (u64)__float_as_uint(x) | ((u64)__float_as_uint(y) << 32);
}
// order-preserving float->uint (monotone increasing)
__device__ __forceinline__ u32 ford(float f) {
    u32 u = __float_as_uint(f);
    return (u & 0x80000000u) ? ~u : (u | 0x80000000u);
}

// Branch-free sorted insert: values in regs, indices in column-major smem.
// Strict '>' keeps (value desc, index asc) order for index-ordered streams.
__device__ __forceinline__ void insert_bf(float (&tv)[KK], int (*ti)[256],
                                          int tid, float v, int idx) {
    #pragma unroll
    for (int p = 0; p < KK; p++) {
        bool sw = v > tv[p];
        float nv = sw ? v : tv[p];
        float cv = sw ? tv[p] : v;
        int oi = ti[p][tid];
        int ni = sw ? idx : oi;
        int ci = sw ? oi : idx;
        tv[p] = nv; v = cv;
        ti[p][tid] = ni; idx = ci;
    }
}

// ---------------- x -> xT (B,N,4) + squared norms ----------------
__global__ void prep_x_kernel(const float* __restrict__ x) {
    int i = blockIdx.x * blockDim.x + threadIdx.x;   // b*NP+n
    if (i >= NB*NP) return;
    int b = i >> 13, n = i & (NP - 1);
    const float* xb = x + (size_t)b * 3 * NP;
    float a0 = xb[0*NP + n], a1 = xb[1*NP + n], a2 = xb[2*NP + n];
    float4 v = make_float4(a0, a1, a2, 0.f);
    *reinterpret_cast<float4*>(d_xT + (size_t)i * 4) = v;
    d_sqn[i] = a0*a0 + a1*a1 + a2*a2;
}

// ---------------- layer0 G/A from x (W0 is 64x6) ----------------
__global__ void ga0_kernel(const float* __restrict__ W0) {
    int b = blockIdx.y;
    int n0 = blockIdx.x * 16;
    int o = threadIdx.x;         // 0..127
    float w0, w1, w2;
    if (o < 64) { w0 = W0[o*6+0]; w1 = W0[o*6+1]; w2 = W0[o*6+2]; }
    else { int u = o - 64;
           w0 = W0[u*6+3] - W0[u*6+0];
           w1 = W0[u*6+4] - W0[u*6+1];
           w2 = W0[u*6+5] - W0[u*6+2]; }
    float* dst = (o < 64) ? d_G : d_A;
    int oo = o & 63;
    #pragma unroll
    for (int p = 0; p < 16; p++) {
        float4 xv = *reinterpret_cast<const float4*>(d_xT + ((size_t)b*NP + n0 + p) * 4);
        float v = w0*xv.x + w1*xv.y + w2*xv.z;
        dst[((size_t)b*NP + n0 + p)*DD + oo] = v;
    }
}

// ---------------- kNN v3: branch-free buffered top-20 ----------------
template<int C>
__global__ void __launch_bounds__(256, 2) knn3_kernel() {
    const int b = blockIdx.z, s = blockIdx.y;
    const int tid = threadIdx.x;
    const int q = blockIdx.x * 256 + tid;
    const float* pts = (C == 4) ? d_xT : d_hfT;
    const float* P = pts + (size_t)b * NP * C;

    __shared__ __align__(16) float smC[TS * C];
    __shared__ float smS[TS];
    __shared__ u64 sBuf[BUF][256];
    __shared__ int sTi[KK][256];

    // query vector in packed f32x2 registers
    u64 qp[C/2];
    #pragma unroll
    for (int j = 0; j < C/4; j++) {
        float4 v = *reinterpret_cast<const float4*>(P + (size_t)q * C + 4*j);
        qp[2*j]   = packf2(v.x, v.y);
        qp[2*j+1] = packf2(v.z, v.w);
    }

    float tv[KK];
    #pragma unroll
    for (int i = 0; i < KK; i++) { tv[i] = -INFINITY; sTi[i][tid] = 0x7FFFFFFF; }
    float thrK = -INFINITY;
    int cnt = 0;

    const u32 saTile = (u32)__cvta_generic_to_shared(smC);
    const u32 saBuf  = (u32)__cvta_generic_to_shared(sBuf) + tid * 8;

    for (int tile = 0; tile < CH / TS; tile++) {
        const int m0 = s * CH + tile * TS;
        __syncthreads();
        const float4* src = reinterpret_cast<const float4*>(P + (size_t)m0 * C);
        for (int t = tid; t < TS * C / 4; t += 256)
            reinterpret_cast<float4*>(smC)[t] = src[t];
        if (tid < TS) smS[tid] = d_sqn[b*NP + m0 + tid];
        __syncthreads();

        #pragma unroll 1
        for (int t = 0; t < TS; t++) {
            u32 ca = saTile + (u32)(t * C * 4);
            float key;
            if constexpr (C >= 8) {
                u64 a0 = 0ull, a1 = 0ull, a2 = 0ull, a3 = 0ull;
                #pragma unroll
                for (int j = 0; j < C/4; j++) {
                    u64 x0, x1;
                    asm("ld.shared.v2.b64 {%0,%1},[%2];"
                        : "=l"(x0), "=l"(x1) : "r"(ca + j*16));
                    if ((j & 1) == 0) { a0 = ffma2(qp[2*j], x0, a0); a1 = ffma2(qp[2*j+1], x1, a1); }
                    else              { a2 = ffma2(qp[2*j], x0, a2); a3 = ffma2(qp[2*j+1], x1, a3); }
                }
                U64F2 r; r.u = fadd2(fadd2(a0, a1), fadd2(a2, a3));
                float dot = r.f.x + r.f.y;
                key = fmaf(2.0f, dot, -smS[t]);
            } else {
                u64 x0, x1;
                asm("ld.shared.v2.b64 {%0,%1},[%2];"
                    : "=l"(x0), "=l"(x1) : "r"(ca));
                U64F2 r; r.u = fadd2(ffma2(qp[0], x0, 0ull), ffma2(qp[1], x1, 0ull));
                float dot = r.f.x + r.f.y;
                key = fmaf(2.0f, dot, -smS[t]);
            }
            // branch-free predicated append to buffer
            u64 pkd = ((u64)__float_as_uint(key) << 32) | (u32)(m0 + t);
            u32 addr = saBuf + (u32)cnt * (256u * 8u);
            asm volatile("{ .reg .pred p; setp.gt.f32 p, %1, %2;"
                         "  @p st.shared.b64 [%0], %3; }"
                         :: "r"(addr), "f"(key), "f"(thrK), "l"(pkd) : "memory");
            cnt += (key > thrK);

            if (__any_sync(0xffffffffu, cnt == BUF)) {
                #pragma unroll 1
                for (int e = 0; e < cnt; e++) {
                    u64 pk = sBuf[e][tid];
                    insert_bf(tv, sTi, tid,
                              __uint_as_float((u32)(pk >> 32)), (int)(u32)pk);
                }
                cnt = 0; thrK = tv[KK-1];
            }
        }
    }
    #pragma unroll 1
    for (int e = 0; e < cnt; e++) {
        u64 pk = sBuf[e][tid];
        insert_bf(tv, sTi, tid, __uint_as_float((u32)(pk >> 32)), (int)(u32)pk);
    }

    size_t off = ((size_t)(b*NP + q) * NS + s) * KK;
    #pragma unroll
    for (int i = 0; i < KK; i++)
        d_scP[off+i] = ((u64)ford(tv[i]) << 32) | (u32)(~(u32)sTi[i][tid]);
}

// ---------------- merge per-chunk packed lists -> final top-20 ----------------
__global__ void merge_kernel() {
    int i = blockIdx.x * blockDim.x + threadIdx.x;   // b*NP+n
    if (i >= NB*NP) return;
    u64 tq[KK];
    #pragma unroll
    for (int k = 0; k < KK; k++) tq[k] = 0ull;
    const ulonglong2* src =
        reinterpret_cast<const ulonglong2*>(d_scP + (size_t)i * NS * KK);
    #pragma unroll 1
    for (int e = 0; e < NS*KK/2; e++) {
        ulonglong2 pr = src[e];
        #pragma unroll
        for (int h = 0; h < 2; h++) {
            u64 v = h ? pr.y : pr.x;
            if (v > tq[KK-1]) {
                #pragma unroll
                for (int p = 0; p < KK; p++) {
                    bool sw = v > tq[p];
                    u64 a = sw ? v : tq[p];
                    v = sw ? tq[p] : v;
                    tq[p] = a;
                }
            }
        }
    }
    #pragma unroll
    for (int k = 0; k < KK; k++)
        d_nidx[(size_t)i*KK + k] = (int)(~(u32)tq[k]);
}

// ---------------- gather-max + BN + lrelu -> h (channel-major output) ------
__global__ void gather_kernel(const float* __restrict__ gamma,
                              const float* __restrict__ beta,
                              const float* __restrict__ mean,
                              const float* __restrict__ var,
                              float* __restrict__ out) {
    int b = blockIdx.y;
    int j = threadIdx.x >> 6;     // point within block (0..3)
    int o = threadIdx.x & 63;
    int n = blockIdx.x * 4 + j;

    __shared__ int sIdx[4 * KK];
    if (threadIdx.x < 4 * KK) {
        int jj = threadIdx.x / KK, kk = threadIdx.x % KK;
        sIdx[threadIdx.x] = d_nidx[((size_t)b*NP + blockIdx.x*4 + jj)*KK + kk];
    }
    __syncthreads();

    const float* Gb = d_G + (size_t)b * NP * DD;
    float mx = -INFINITY;
    #pragma unroll
    for (int k = 0; k < KK; k++)
        mx = fmaxf(mx, Gb[(size_t)sIdx[j*KK + k] * DD + o]);

    float z = d_A[((size_t)b*NP + n)*DD + o] + mx;
    float sc = gamma[o] * rsqrtf(var[o] + EPSB);
    z = (z - mean[o]) * sc + beta[o];
    z = (z >= 0.f) ? z : 0.2f * z;
    out[((size_t)b*DD + o)*NP + n] = z;
}

// ---------------- fuse: hf = elu(Wf * [h; rep]) -> point-major ----------------
__global__ void fuse_kernel(const float* __restrict__ h,
                            const float* __restrict__ rep,
                            const float* __restrict__ W) {
    int b = blockIdx.y;
    int n0 = blockIdx.x * 16;
    int o = threadIdx.x;          // 0..63

    __shared__ float sWT[128][64];
    __shared__ float sIn[128][16];
    for (int t = threadIdx.x; t < 128*64; t += 64) {
        int c = t >> 6, oo = t & 63;
        sWT[c][oo] = W[oo*128 + c];
    }
    for (int t = threadIdx.x; t < 128*16; t += 64) {
        int c = t >> 4, p = t & 15;
        sIn[c][p] = (c < 64) ? h  [((size_t)b*DD + c)*NP + n0 + p]
                             : rep[((size_t)b*DD + (c-64))*NP + n0 + p];
    }
    __syncthreads();

    float acc[16];
    #pragma unroll
    for (int p = 0; p < 16; p++) acc[p] = 0.f;
    for (int c = 0; c < 128; c++) {
        float w = sWT[c][o];
        #pragma unroll
        for (int p = 0; p < 16; p++) acc[p] = fmaf(w, sIn[c][p], acc[p]);
    }
    #pragma unroll
    for (int p = 0; p < 16; p++) {
        float z = acc[p];
        z = (z > 0.f) ? z : expm1f(z);
        d_hfT[((size_t)b*NP + n0 + p)*DD + o] = z;
    }
}

// ---------------- squared norms of hfT ----------------
__global__ void sqnorm_kernel() {
    int i = blockIdx.x * blockDim.x + threadIdx.x;   // point index
    if (i >= NB*NP) return;
    const float4* r = reinterpret_cast<const float4*>(d_hfT + (size_t)i * DD);
    float s = 0.f;
    #pragma unroll
    for (int j = 0; j < 16; j++) {
        float4 v = r[j];
        s += v.x*v.x + v.y*v.y + v.z*v.z + v.w*v.w;
    }
    d_sqn[i] = s;
}

// ---------------- G/A from hfT (W is 64x128) ----------------
__global__ void ga_kernel(const float* __restrict__ W) {
    int b = blockIdx.y;
    int n0 = blockIdx.x * 16;
    int o = threadIdx.x;          // 0..127

    __shared__ float sWT[64][128];   // [c][o128]
    __shared__ float sIn[16][64];
    for (int c = 0; c < 64; c++) {
        float w = (o < 64) ? W[o*128 + c]
                           : (W[(o-64)*128 + 64 + c] - W[(o-64)*128 + c]);
        sWT[c][o] = w;
    }
    for (int t = threadIdx.x; t < 16*64; t += 128) {
        int p = t >> 6, c = t & 63;
        sIn[p][c] = d_hfT[((size_t)b*NP + n0 + p)*DD + c];
    }
    __syncthreads();

    float acc[16];
    #pragma unroll
    for (int p = 0; p < 16; p++) acc[p] = 0.f;
    for (int c = 0; c < 64; c++) {
        float w = sWT[c][o];
        #pragma unroll
        for (int p = 0; p < 16; p++) acc[p] = fmaf(w, sIn[p][c], acc[p]);
    }
    float* dst = (o < 64) ? d_G : d_A;
    int oo = o & 63;
    #pragma unroll
    for (int p = 0; p < 16; p++)
        dst[((size_t)b*NP + n0 + p)*DD + oo] = acc[p];
}

// ---------------- launch ----------------
extern "C" void kernel_launch(void* const* d_in, const int* in_sizes, int n_in,
                              void* d_out, int out_size) {
    (void)in_sizes; (void)n_in; (void)out_size;
    const float* x     = (const float*)d_in[0];
    const float* reps  = (const float*)d_in[1];
    const float* w0    = (const float*)d_in[2];
    const float* convw = (const float*)d_in[3];
    const float* gam   = (const float*)d_in[4];
    const float* bet   = (const float*)d_in[5];
    const float* rm    = (const float*)d_in[6];
    const float* rv    = (const float*)d_in[7];
    const float* fw    = (const float*)d_in[8];
    float* out = (float*)d_out;
    const size_t LSZ = (size_t)NB * DD * NP;

    // layer 0
    prep_x_kernel<<<NB*NP/256, 256>>>(x);
    ga0_kernel<<<dim3(NP/16, NB), 128>>>(w0);
    knn3_kernel<4><<<dim3(NP/256, NS, NB), 256>>>();
    merge_kernel<<<NB*NP/256, 256>>>();
    gather_kernel<<<dim3(NP/4, NB), 256>>>(gam, bet, rm, rv, out);

    // layers 1..3
    for (int i = 0; i < 3; i++) {
        fuse_kernel<<<dim3(NP/16, NB), 64>>>(out + (size_t)i * LSZ,
                                             reps + (size_t)i * LSZ,
                                             fw + (size_t)i * 64 * 128);
        sqnorm_kernel<<<NB*NP/256, 256>>>();
        ga_kernel<<<dim3(NP/16, NB), 128>>>(convw + (size_t)i * 64 * 128);
        knn3_kernel<64><<<dim3(NP/256, NS, NB), 256>>>();
        merge_kernel<<<NB*NP/256, 256>>>();
        gather_kernel<<<dim3(NP/4, NB), 256>>>(gam + (i+1)*64, bet + (i+1)*64,
                                               rm + (i+1)*64, rv + (i+1)*64,
                                               out + (size_t)(i+1) * LSZ);
    }
}